// round 10
// baseline (speedup 1.0000x reference)
#include <cuda_runtime.h>
#include <cstdint>

#define ITEMS_TOTAL 50000
#define DIM         64
#define BATCH       16
#define NPG         50
#define VEC4_PER_ROW (DIM / 4)     // 16 float4 per row
#define WINDOW       32            // rows per window
#define THREADS      512           // 32 row-slots x 16 lanes
#define N_WINDOWS    ((ITEMS_TOTAL + WINDOW - 1) / WINDOW)   // 1563
#define GRID         296           // 2 CTAs per SM x 148 SMs
#define MAXW         ((N_WINDOWS + GRID - 1) / GRID)         // 6

// Persistent-style fused kernel: each CTA stages the 800 node indices ONCE,
// then loops over up to MAXW row-windows (stride gridDim.x). Window-touched
// flags are computed during the compact pass, so untouched window iterations
// run barrier-free and their emb loads pipeline across iterations.
__global__ void __launch_bounds__(THREADS)
fused_kernel(const float4* __restrict__ emb4,
             const float*  __restrict__ feat,      // (BATCH*NPG, DIM)
             const float*  __restrict__ alpha,     // (ITEMS_TOTAL, 1)
             const void*   __restrict__ nodes_raw, // int32 or int64, 800 entries
             float4*       __restrict__ out4) {    // (BATCH, ITEMS_TOTAL, DIM/4)
    __shared__ int s_stage[BATCH * NPG];         // raw first 3200 bytes
    __shared__ int s_idx[BATCH * NPG];           // node indices as int32
    __shared__ int s_pos[WINDOW][BATCH + 1];     // last pos per (row,b); pad
    __shared__ int s_not64;
    __shared__ int s_any[MAXW];                  // touched flag per owned window

    const int tid   = threadIdx.x;
    const int rslot = tid >> 4;                  // 0..31 local row slot
    const int b_id  = tid & 15;                  // 0..15 batch / lane
    const int bid   = (int)blockIdx.x;

    if (tid < MAXW) s_any[tid] = 0;
    if (tid == 0)   s_not64 = 0;

    const int* a32 = (const int*)nodes_raw;

    // Phase 1a: stage first 3200 bytes (valid under both dtypes).
    for (int k = tid; k < BATCH * NPG; k += THREADS) s_stage[k] = a32[k];
    __syncthreads();

    // Phase 1b: dtype detection — int64 LE with values < 50000 has all-zero
    // high words in the first 400 pairs.
    for (int k = tid; k < 400; k += THREADS) {
        if (s_stage[2 * k + 1] != 0) s_not64 = 1;   // benign race
    }
    __syncthreads();
    const bool is64 = (s_not64 == 0);

    // Phase 1c: compact to int32; flag owned windows that contain a node.
    for (int k = tid; k < BATCH * NPG; k += THREADS) {
        int val;
        if (is64) {
            val = (k < 400) ? s_stage[2 * k] : a32[2 * k];  // int64 buf = 6400 B
        } else {
            val = s_stage[k];
        }
        s_idx[k] = val;
        int wg  = val >> 5;                    // window containing this node
        int rel = wg - bid;
        if (rel >= 0 && rel % GRID == 0) {
            int i = rel / GRID;
            if (i < MAXW) s_any[i] = 1;        // benign race
        }
    }
    __syncthreads();

    const long long n4 = (long long)ITEMS_TOTAL * VEC4_PER_ROW;   // 800,000

    for (int i = 0; i < MAXW; i++) {
        const int w = bid + i * GRID;
        if (w >= N_WINDOWS) break;
        const int row = w * WINDOW + rslot;
        const bool ok = (row < ITEMS_TOTAL);
        const long long t = (long long)row * VEC4_PER_ROW + b_id;

        if (!s_any[i]) {
            // Untouched window: barrier-free 16-way broadcast store.
            if (ok) {
                float4 v = emb4[t];
#pragma unroll
                for (int b = 0; b < BATCH; b++)
                    __stcs(&out4[(long long)b * n4 + t], v);
            }
        } else {
            // Touched window: rebuild s_pos for these 32 rows.
            __syncthreads();   // protect s_pos reuse from a prior touched window
            int p = -1;
            const int base = b_id * NPG;
#pragma unroll 10
            for (int jj = 0; jj < NPG; jj++) {
                if (s_idx[base + jj] == row) p = base + jj;  // forward => last
            }
            s_pos[rslot][b_id] = p;
            __syncthreads();

            if (ok) {
                float4 v = emb4[t];
                bool touched = false;
#pragma unroll
                for (int b = 0; b < BATCH; b++) touched |= (s_pos[rslot][b] >= 0);

                if (!touched) {
#pragma unroll
                    for (int b = 0; b < BATCH; b++)
                        __stcs(&out4[(long long)b * n4 + t], v);
                } else {
                    const float a  = alpha[row];
                    const float na = 1.0f - a;
#pragma unroll
                    for (int b = 0; b < BATCH; b++) {
                        float4 wv = v;
                        int p2 = s_pos[rslot][b];
                        if (p2 >= 0) {
                            const float4* f4 = reinterpret_cast<const float4*>(
                                feat + (long long)p2 * DIM);
                            float4 f = f4[b_id];
                            wv.x = fmaf(a, f.x, na * v.x);
                            wv.y = fmaf(a, f.y, na * v.y);
                            wv.z = fmaf(a, f.z, na * v.z);
                            wv.w = fmaf(a, f.w, na * v.w);
                        }
                        __stcs(&out4[(long long)b * n4 + t], wv);
                    }
                }
            }
        }
    }
}

extern "C" void kernel_launch(void* const* d_in, const int* in_sizes, int n_in,
                              void* d_out, int out_size) {
    // 0: nodes (int32/int64)  1: nodes_output f32  2: emb_table f32  3: alpha f32
    const void*  nodes = d_in[0];
    const float* feat  = (const float*)d_in[1];
    const float* emb   = (const float*)d_in[2];
    const float* alpha = (const float*)d_in[3];
    float*       out   = (float*)d_out;

    fused_kernel<<<GRID, THREADS>>>(
        reinterpret_cast<const float4*>(emb), feat, alpha, nodes,
        reinterpret_cast<float4*>(out));
}

// round 14
// speedup vs baseline: 1.1001x; 1.1001x over previous
#include <cuda_runtime.h>
#include <cstdint>

#define ITEMS_TOTAL 50000
#define DIM         64
#define BATCH       16
#define NPG         50
#define VEC4_PER_ROW (DIM / 4)   // 16 float4 per row
#define ROWS_PER_CTA 32
#define THREADS      512         // 32 rows x 16 lanes
#define N4           (ITEMS_TOTAL * VEC4_PER_ROW)   // 800,000 float4 per slice

// R5 structure (best known: 33.28us) with all addressing strength-reduced to
// 32-bit. Max byte offset 204.8MB < 2^31, so 64-bit index math is pure waste;
// the 16-way store loop becomes one address chain with constant strides.
__global__ void __launch_bounds__(THREADS)
fused_kernel(const float4* __restrict__ emb4,
             const float*  __restrict__ feat,      // (BATCH*NPG, DIM)
             const float*  __restrict__ alpha,     // (ITEMS_TOTAL, 1)
             const void*   __restrict__ nodes_raw, // int32 or int64, 800 entries
             float4*       __restrict__ out4) {    // (BATCH, ITEMS_TOTAL, DIM/4)
    __shared__ int s_stage[BATCH * NPG];            // raw first 3200 bytes
    __shared__ int s_idx[BATCH * NPG];              // node indices as int32
    __shared__ int s_pos[ROWS_PER_CTA][BATCH + 1];  // last pos per (row,b); pad
    __shared__ int s_not64;
    __shared__ int s_any;                           // any node in this CTA's rows?

    const int tid  = threadIdx.x;
    const int r    = tid >> 4;                      // 0..31 local row
    const int b_id = tid & 15;                      // 0..15 batch / lane
    const int row_base = (int)blockIdx.x * ROWS_PER_CTA;
    const int row  = row_base + r;
    const bool row_ok = (row < ITEMS_TOTAL);

    // ---- Prefetch emb row chunk (independent of smem phases) ----
    const int t = row * VEC4_PER_ROW + b_id;        // < 800,016, fits int
    float4 v;
    if (row_ok) v = emb4[t];

    const int* a32 = (const int*)nodes_raw;
    if (tid == 0) { s_not64 = 0; s_any = 0; }

    // Phase 1a: stage first 3200 bytes (valid under both dtypes).
    for (int k = tid; k < BATCH * NPG; k += THREADS) s_stage[k] = a32[k];
    __syncthreads();

    // Phase 1b: dtype detection — int64 LE with values < 50000 has all-zero
    // high words in the first 400 pairs.
    for (int k = tid; k < 400; k += THREADS) {
        if (s_stage[2 * k + 1] != 0) s_not64 = 1;   // benign race
    }
    __syncthreads();
    const bool is64 = (s_not64 == 0);

    // Phase 1c: compact to int32 indices; flag if any falls in our row window.
    for (int k = tid; k < BATCH * NPG; k += THREADS) {
        int val;
        if (is64) {
            val = (k < 400) ? s_stage[2 * k] : a32[2 * k];  // int64 buf = 6400 B
        } else {
            val = s_stage[k];
        }
        s_idx[k] = val;
        if ((unsigned)(val - row_base) < (unsigned)ROWS_PER_CTA) s_any = 1;
    }
    __syncthreads();

    // Single base pointer; batch slices step by constant N4 float4.
    float4* o = out4 + t;

    if (s_any) {
        // Phase 2: thread (r, b) finds last occurrence of its row in graph b.
        int p = -1;
        const int base = b_id * NPG;
#pragma unroll 10
        for (int jj = 0; jj < NPG; jj++) {
            if (s_idx[base + jj] == row) p = base + jj;  // forward scan => last
        }
        s_pos[r][b_id] = p;
        __syncthreads();

        if (row_ok) {
            bool touched = false;
#pragma unroll
            for (int b = 0; b < BATCH; b++) touched |= (s_pos[r][b] >= 0);

            if (!touched) {
#pragma unroll
                for (int b = 0; b < BATCH; b++)
                    __stcs(o + b * N4, v);
            } else {
                const float a  = alpha[row];
                const float na = 1.0f - a;
#pragma unroll
                for (int b = 0; b < BATCH; b++) {
                    float4 w = v;
                    int p2 = s_pos[r][b];
                    if (p2 >= 0) {
                        const float4* f4 = reinterpret_cast<const float4*>(
                            feat + p2 * DIM);
                        float4 f = f4[b_id];
                        w.x = fmaf(a, f.x, na * v.x);
                        w.y = fmaf(a, f.y, na * v.y);
                        w.z = fmaf(a, f.z, na * v.z);
                        w.w = fmaf(a, f.w, na * v.w);
                    }
                    __stcs(o + b * N4, w);
                }
            }
        }
    } else if (row_ok) {
        // Untouched CTA: pure 16-way broadcast store off one address chain.
#pragma unroll
        for (int b = 0; b < BATCH; b++)
            __stcs(o + b * N4, v);
    }
}

extern "C" void kernel_launch(void* const* d_in, const int* in_sizes, int n_in,
                              void* d_out, int out_size) {
    // 0: nodes (int32/int64)  1: nodes_output f32  2: emb_table f32  3: alpha f32
    const void*  nodes = d_in[0];
    const float* feat  = (const float*)d_in[1];
    const float* emb   = (const float*)d_in[2];
    const float* alpha = (const float*)d_in[3];
    float*       out   = (float*)d_out;

    const int blocks = (ITEMS_TOTAL + ROWS_PER_CTA - 1) / ROWS_PER_CTA;  // 1563
    fused_kernel<<<blocks, THREADS>>>(
        reinterpret_cast<const float4*>(emb), feat, alpha, nodes,
        reinterpret_cast<float4*>(out));
}